// round 5
// baseline (speedup 1.0000x reference)
#include <cuda_runtime.h>
#include <math.h>

#define K_SIZE 41
#define WBLK   256
// Writer grid: 41*28 = 1148 blocks <= 1184 (148 SMs * 8 blocks @ 256 thr)
// => one wave, and stride = 1148*256 = 293888 = 41*7168 float4s (== 0 mod 41)
// so each thread's pattern float4 is loop-invariant.
#define GRID_MULT 28
#define NBLOCKS   (K_SIZE * GRID_MULT)

// Period-41 table of float4 write patterns, produced by prep kernel.
__device__ float4 g_pat[K_SIZE];

// ---------------------------------------------------------------------------
// Prep: 1 block, 64 threads. Computes padded window, masked circular max ->
// base[41], expands to float4 pattern table, writes the <=3 tail scalars.
// Runs in ~1us; measured to be fully hidden inside harness overhead.
// ---------------------------------------------------------------------------
__global__ void flatdil_prep_kernel(const float* __restrict__ in,
                                    const float* __restrict__ scale_p,
                                    float* __restrict__ out,
                                    long long n)
{
    __shared__ float s_pad[K_SIZE];
    __shared__ float s_base[K_SIZE];

    const int t = threadIdx.x;

    // Python: missing = K_SIZE - n; a = -(missing // 2 + 2)  (floor division)
    const long long missing = (long long)K_SIZE - n;
    const long long a = -((missing >> 1) + 2);   // arithmetic shift == floor div

    if (t < K_SIZE) {
        s_pad[t] = in[a + (long long)t];
    }
    __syncthreads();

    if (t < K_SIZE) {
        const float scale = *scale_p;
        float acc = -INFINITY;
        #pragma unroll
        for (int j = 0; j < K_SIZE; ++j) {
            // z[j] = -20 + j  (linspace(-20,20,41) has exact unit step)
            const float zj = (float)(j - 20);
            if (fabsf(zj) <= scale) {
                int idx = t + j;
                if (idx >= K_SIZE) idx -= K_SIZE;
                acc = fmaxf(acc, s_pad[idx]);
            }
        }
        s_base[t] = acc;
    }
    __syncthreads();

    if (t < K_SIZE) {
        // g_pat[p] covers output floats 4p..4p+3 (period in float4s = 41)
        int i0 = (4 * t) % K_SIZE;
        int i1 = i0 + 1; if (i1 >= K_SIZE) i1 -= K_SIZE;
        int i2 = i1 + 1; if (i2 >= K_SIZE) i2 -= K_SIZE;
        int i3 = i2 + 1; if (i3 >= K_SIZE) i3 -= K_SIZE;
        float4 v;
        v.x = s_base[i0];
        v.y = s_base[i1];
        v.z = s_base[i2];
        v.w = s_base[i3];
        g_pat[t] = v;
    }

    // Tail: elements not covered by the float4 writer (<= 3 of them)
    if (t == 0) {
        long long n4 = n >> 2;
        for (long long k = n4 * 4; k < n; ++k) {
            out[k] = s_base[(int)(k % K_SIZE)];
        }
    }
}

// ---------------------------------------------------------------------------
// Writer: one wave, loop-invariant value in registers, hot loop is pure
// STG.128 + index add. Prologue (~0.3us): stage 656B of g_pat to smem,
// one LDS.128 per thread, one %41.
// ---------------------------------------------------------------------------
__global__ void __launch_bounds__(WBLK, 8)
flatdil_write_kernel(float4* __restrict__ out4, unsigned int n4)
{
    __shared__ float4 s_pat[K_SIZE];
    const unsigned int t = threadIdx.x;
    if (t < K_SIZE) s_pat[t] = g_pat[t];
    __syncthreads();

    const unsigned int stride = NBLOCKS * WBLK;        // 293888 = 41*7168
    unsigned int i = blockIdx.x * WBLK + t;

    if (i < n4) {
        const float4 v = s_pat[i % K_SIZE];            // computed ONCE
        #pragma unroll 4
        for (; i < n4; i += stride) {
            out4[i] = v;                               // pure STG.128
        }
    }
}

// ---------------------------------------------------------------------------
extern "C" void kernel_launch(void* const* d_in, const int* in_sizes, int n_in,
                              void* d_out, int out_size)
{
    const float* in      = (const float*)d_in[0];
    const float* scale_p = (const float*)d_in[1];
    float* out           = (float*)d_out;

    const long long n  = (long long)in_sizes[0];
    const long long n4 = n >> 2;

    flatdil_prep_kernel<<<1, 64>>>(in, scale_p, out, n);

    if (n4 > 0) {
        flatdil_write_kernel<<<NBLOCKS, WBLK>>>((float4*)out, (unsigned int)n4);
    }
}

// round 6
// speedup vs baseline: 1.1707x; 1.1707x over previous
#include <cuda_runtime.h>
#include <math.h>

#define K_SIZE 41
#define WBLK   256
#define VPT    2    // float8 (32B) stores per thread

// Period-41 table of float8 write patterns (as pairs of float4),
// produced by prep kernel. g_pat8[p] covers output floats 8p..8p+7.
__device__ float4 g_pat8[K_SIZE][2];

// ---------------------------------------------------------------------------
// Prep: 1 block, 64 threads. Computes padded window, masked circular max ->
// base[41], expands to float8 pattern table, writes the tail scalars
// (n mod 8 elements). Measured to be fully hidden in harness overhead.
// ---------------------------------------------------------------------------
__global__ void flatdil_prep_kernel(const float* __restrict__ in,
                                    const float* __restrict__ scale_p,
                                    float* __restrict__ out,
                                    long long n)
{
    __shared__ float s_pad[K_SIZE];
    __shared__ float s_base[K_SIZE];

    const int t = threadIdx.x;

    // Python: missing = K_SIZE - n; a = -(missing // 2 + 2)  (floor division)
    const long long missing = (long long)K_SIZE - n;
    const long long a = -((missing >> 1) + 2);   // arithmetic shift == floor div

    if (t < K_SIZE) {
        s_pad[t] = in[a + (long long)t];
    }
    __syncthreads();

    if (t < K_SIZE) {
        const float scale = *scale_p;
        float acc = -INFINITY;
        #pragma unroll
        for (int j = 0; j < K_SIZE; ++j) {
            // z[j] = -20 + j  (linspace(-20,20,41) has exact unit step)
            const float zj = (float)(j - 20);
            if (fabsf(zj) <= scale) {
                int idx = t + j;
                if (idx >= K_SIZE) idx -= K_SIZE;
                acc = fmaxf(acc, s_pad[idx]);
            }
        }
        s_base[t] = acc;
    }
    __syncthreads();

    if (t < K_SIZE) {
        // g_pat8[p][h].{x,y,z,w} = base[(8p + 4h + c) % 41]
        float tmp[8];
        #pragma unroll
        for (int c = 0; c < 8; ++c) {
            int idx = (8 * t + c) % K_SIZE;
            tmp[c] = s_base[idx];
        }
        g_pat8[t][0] = make_float4(tmp[0], tmp[1], tmp[2], tmp[3]);
        g_pat8[t][1] = make_float4(tmp[4], tmp[5], tmp[6], tmp[7]);
    }

    // Tail: elements not covered by the float8 writer (n mod 8 of them)
    if (t == 0) {
        long long n8 = n >> 3;
        for (long long k = n8 * 8; k < n; ++k) {
            out[k] = s_base[(int)(k % K_SIZE)];
        }
    }
}

// ---------------------------------------------------------------------------
// Writer: VPT x st.global.cs.v8.f32 (32B) per thread. Pattern staged in
// 1312B of shared; each thread does VPT mods + VPT*2 LDS.128 in the
// prologue, then straight-line 256-bit streaming stores. Multi-wave grid
// (8192 blocks) so prologues overlap other blocks' stores.
// ---------------------------------------------------------------------------
__global__ void __launch_bounds__(WBLK, 8)
flatdil_write_kernel(float* __restrict__ out, unsigned int n8)
{
    __shared__ float4 s_pat[K_SIZE][2];
    const unsigned int t = threadIdx.x;
    // stage 82 float4s with the first 82 threads
    if (t < K_SIZE * 2) {
        s_pat[t >> 1][t & 1] = g_pat8[t >> 1][t & 1];
    }
    __syncthreads();

    const unsigned int base = blockIdx.x * (WBLK * VPT) + t;

    #pragma unroll
    for (int v = 0; v < VPT; ++v) {
        const unsigned int i = base + v * WBLK;    // float8 index, coalesced per warp
        if (i < n8) {
            const unsigned int m = i % K_SIZE;
            const float4 lo = s_pat[m][0];
            const float4 hi = s_pat[m][1];
            float* p = out + (size_t)i * 8;
            asm volatile(
                "st.global.cs.v8.f32 [%0], {%1,%2,%3,%4,%5,%6,%7,%8};"
                :: "l"(p),
                   "f"(lo.x), "f"(lo.y), "f"(lo.z), "f"(lo.w),
                   "f"(hi.x), "f"(hi.y), "f"(hi.z), "f"(hi.w)
                : "memory");
        }
    }
}

// ---------------------------------------------------------------------------
extern "C" void kernel_launch(void* const* d_in, const int* in_sizes, int n_in,
                              void* d_out, int out_size)
{
    const float* in      = (const float*)d_in[0];
    const float* scale_p = (const float*)d_in[1];
    float* out           = (float*)d_out;

    const long long n  = (long long)in_sizes[0];
    const long long n8 = n >> 3;

    flatdil_prep_kernel<<<1, 64>>>(in, scale_p, out, n);

    if (n8 > 0) {
        const unsigned int per_block = WBLK * VPT;
        const unsigned int blocks = (unsigned int)((n8 + per_block - 1) / per_block);
        flatdil_write_kernel<<<blocks, WBLK>>>(out, (unsigned int)n8);
    }
}